// round 11
// baseline (speedup 1.0000x reference)
#include <cuda_runtime.h>
#include <cuda_fp16.h>

#define NBINS 32
#define NROWS 34                  /* row 0 = identity-low, 1..32 real, 33 = identity-high */
#define NDIM 64
#define NCELL 66                  /* cells 0..65 via floor(65*sat(0.1v+0.5)) */
#define RMIN (-5.0f)
#define THREADS 512
#define CTAS_PER_SM 4             /* 2048 thr/SM = 64 warps = HW max */
#define BLOCKS 592                /* 148 SMs x 4 CTAs: one persistent wave */
#define STRIDE (BLOCKS * THREADS) /* 303104, compile-time, ==0 mod 64 */
#define U 4                       /* pipeline batch (32-reg budget) */

/* smem layout (all [row][dim]: consecutive lanes = consecutive dims = no
   bank conflicts regardless of divergent row index):
   rec  [NROWS][NDIM] float4 {xk, yk, (A,dk) f16x2, (C,D) f16x2}  34816 B
   cell [NCELL][NDIM] float  (bnd | jlo in low 6 bits)            16896 B
   hi   [NDIM] float (top knot, needed only for cell build)         256 B
   -> 51968 B, 4 CTAs/SM (207.9 KB of 228 KB) */
#define OFF_CELL 34816
#define OFF_HI   (34816 + 16896)
#define SMEM_BYTES (OFF_HI + 256)

__device__ __forceinline__ int bin_of(float v, const float* __restrict__ celld)
{
    /* FFMA.SAT clamps to [0,1]; one FMUL + F2I replaces guess + 2 clamps */
    const float ts = __saturatef(fmaf(v, 0.1f, 0.5f));
    const int c = __float2int_rd(ts * 65.0f);          /* [0,65] */
    const int b = __float_as_int(celld[c * NDIM]);
    /* low 6 bits of boundary float hold jlo; ~63-ulp boundary shift is
       harmless: the spline is C1 across knots */
    return (b & 63) + ((v >= __int_as_float(b)) ? 1 : 0);
}

__device__ __forceinline__ float eval1(float v, int j,
                                       const float4* __restrict__ recd)
{
    const float4 r = recd[j * NDIM];
    const float u = v - r.x;
    const float2 ab = __half22float2(*(const __half2*)&r.z);  /* A, dk */
    const float2 cd = __half22float2(*(const __half2*)&r.w);  /* C, D  */
    const float num = u * fmaf(ab.x, u, ab.y);
    const float den = fmaf(u, fmaf(cd.x, u, cd.y), 1.0f);
    return r.y + __fdividef(num, den);  /* identity rows: y = 0 + v/1 = v */
}

__device__ __forceinline__ void eval_batch(
    const float* __restrict__ xv,
    const float* __restrict__ celld,
    const float4* __restrict__ recd,
    float* __restrict__ out, int i)
{
    int jj[U];
    #pragma unroll
    for (int u = 0; u < U; ++u) jj[u] = bin_of(xv[u], celld);
    #pragma unroll
    for (int u = 0; u < U; ++u)
        out[i + u * STRIDE] = eval1(xv[u], jj[u], recd);
}

__global__ __launch_bounds__(THREADS, CTAS_PER_SM) void rqspline_kernel(
    const float* __restrict__ x,
    const float* __restrict__ bw,
    const float* __restrict__ bh,
    const float* __restrict__ ks,
    float* __restrict__ out,
    int total)
{
    extern __shared__ __align__(16) char smem[];
    float4* rec  = (float4*)smem;
    float*  cell = (float*) (smem + OFF_CELL);
    float*  hi   = (float*) (smem + OFF_HI);

    const int t = threadIdx.x;
    const int tid = blockIdx.x * THREADS + t;

    /* ---- prefetch batch 0 BEFORE table build: LDGs fly during build ---- */
    float xc[U];
    const bool full0 = (tid + (U - 1) * STRIDE < total);
    if (full0) {
        #pragma unroll
        for (int u = 0; u < U; ++u) xc[u] = __ldg(x + tid + u * STRIDE);
    }

    /* ---- phase 1: per-dim records; rows 0 and 33 encode identity ---- */
    if (t < NDIM) {
        const __half2 h01_id = __floats2half2_rn(0.0f, 1.0f);  /* A=0, dk=1 */
        const __half2 h23_id = __floats2half2_rn(0.0f, 0.0f);  /* C=0, D=0  */
        float4 rid;
        rid.x = 0.0f; rid.y = 0.0f;
        rid.z = __uint_as_float(*(const unsigned*)&h01_id);
        rid.w = __uint_as_float(*(const unsigned*)&h23_id);
        rec[t] = rid;
        rec[(NROWS - 1) * NDIM + t] = rid;

        float cx = RMIN, cy = RMIN;
        #pragma unroll
        for (int jb = 0; jb < NBINS; ++jb) {
            const float nx = cx + bw[t * NBINS + jb];  /* reference fp32 cumsum */
            const float ny = cy + bh[t * NBINS + jb];
            const float wf = nx - cx;
            const float hf = ny - cy;
            const float dk  = (jb == 0) ? 1.0f : ks[t * (NBINS - 1) + jb - 1];
            const float dk1 = (jb == NBINS - 1) ? 1.0f : ks[t * (NBINS - 1) + jb];

            const float s = hf / wf;
            const float c = dk + dk1 - 2.0f * s;
            const float A = (s - dk) / wf;
            const float C = -c / (hf * wf);
            const float D = c / hf;

            float4 r;
            r.x = cx; r.y = cy;
            const __half2 h01 = __floats2half2_rn(A, dk);
            const __half2 h23 = __floats2half2_rn(C, D);
            r.z = __uint_as_float(*(const unsigned*)&h01);
            r.w = __uint_as_float(*(const unsigned*)&h23);
            rec[(jb + 1) * NDIM + t] = r;
            cx = nx; cy = ny;
        }
        hi[t] = cx;                /* kx[32] */
    }
    __syncthreads();

    /* ---- phase 2: cell table; boundaries read from rec[j+1].x ---- */
    const float* recf = (const float*)rec;
    for (int e = t; e < NCELL * NDIM; e += THREADS) {
        const int c = e >> 6, d = e & (NDIM - 1);
        float bnd; int jlo;
        if (c == 0) {              /* spans (-inf,-5) U [-5, cell-end) */
            bnd = RMIN; jlo = 0;   /* v<-5 -> row 0; v>=-5 -> row 1 */
        } else {
            /* kx(j) for j in 1..31 lives at rec[j+1].x; kx(32) = hi */
            const float cs = RMIN + (float)c * (10.0f / 65.0f);
            int j0 = min(c >> 1, NBINS - 1);
            while (j0 > 0 &&
                   recf[((j0 + 1) << 8) + (d << 2)] > cs) --j0;
            while (j0 < NBINS - 1 &&
                   recf[((j0 + 2) << 8) + (d << 2)] <= cs) ++j0;
            jlo = j0 + 1;
            bnd = (j0 + 1 < NBINS) ? recf[((j0 + 2) << 8) + (d << 2)] : hi[d];
        }
        cell[c * NDIM + d] =
            __int_as_float((__float_as_int(bnd) & ~63) | jlo);
    }
    __syncthreads();

    /* ---- phase 3: software-pipelined streaming eval ---- */
    const int d = tid & (NDIM - 1);      /* loop-invariant: STRIDE % 64 == 0 */
    const float4* recd  = rec  + d;
    const float*  celld = cell + d;

    int i = tid;
    for (; i + (2 * U - 1) * STRIDE < total; i += U * STRIDE) {
        float xn[U];
        #pragma unroll
        for (int u = 0; u < U; ++u)          /* next batch LDGs in flight */
            xn[u] = __ldg(x + i + (U + u) * STRIDE);
        eval_batch(xc, celld, recd, out, i);
        #pragma unroll
        for (int u = 0; u < U; ++u) xc[u] = xn[u];
    }
    if (full0 && i + (U - 1) * STRIDE < total) {
        eval_batch(xc, celld, recd, out, i);
        i += U * STRIDE;
    }
    for (; i < total; i += STRIDE) {
        const float v = __ldg(x + i);
        out[i] = eval1(v, bin_of(v, celld), recd);
    }
}

extern "C" void kernel_launch(void* const* d_in, const int* in_sizes, int n_in,
                              void* d_out, int out_size) {
    const float* x  = (const float*)d_in[0];
    const float* bw = (const float*)d_in[1];
    const float* bh = (const float*)d_in[2];
    const float* ks = (const float*)d_in[3];
    float* out = (float*)d_out;
    const int total = in_sizes[0];

    cudaFuncSetAttribute(rqspline_kernel,
                         cudaFuncAttributeMaxDynamicSharedMemorySize, SMEM_BYTES);
    rqspline_kernel<<<BLOCKS, THREADS, SMEM_BYTES>>>(x, bw, bh, ks, out, total);
}

// round 12
// speedup vs baseline: 1.3176x; 1.3176x over previous
#include <cuda_runtime.h>
#include <cuda_fp16.h>

#define NBINS 32
#define NROWS 34                  /* row 0 = identity-low, 1..32 real, 33 = identity-high */
#define NDIM 64
#define NCELL 66                  /* cells 0..65 via floor(65*sat(0.1v+0.5)) */
#define RMIN (-5.0f)
#define THREADS 768               /* 2 CTAs/SM -> 1536 thr = 48 warps, 40-reg cap */
#define BLOCKS 296                /* 148 SMs x 2 CTAs: one persistent wave */
#define STRIDE (BLOCKS * THREADS) /* 227328, compile-time, ==0 mod 64 */
#define U 6                       /* pipeline batch (proven at 40 regs) */

/* smem layout (all [row][dim]: consecutive lanes = consecutive dims = no
   bank conflicts regardless of divergent row index):
   rec  [NROWS][NDIM] float4 {xk, yk, (A,dk) f16x2, (C,D) f16x2}  34816 B
   cell [NCELL][NDIM] float  (bnd | jlo in low 6 bits)            16896 B
   hi   [NDIM] float (top knot, cell build only)                    256 B
   -> 51968 B, 2 CTAs/SM */
#define OFF_CELL 34816
#define OFF_HI   (34816 + 16896)
#define SMEM_BYTES (OFF_HI + 256)

__device__ __forceinline__ int bin_of(float v, const float* __restrict__ celld)
{
    /* FFMA.SAT folds both clamps: c = floor(65*sat(0.1v+0.5)) in [0,65] */
    const float ts = __saturatef(fmaf(v, 0.1f, 0.5f));
    const int c = __float2int_rd(ts * 65.0f);
    const int b = __float_as_int(celld[c * NDIM]);
    /* low 6 bits of boundary float hold jlo; ~63-ulp boundary shift is
       harmless: the spline is continuous across knots */
    return (b & 63) + ((v >= __int_as_float(b)) ? 1 : 0);
}

__device__ __forceinline__ float eval1(float v, int j,
                                       const float4* __restrict__ recd)
{
    const float4 r = recd[j * NDIM];
    const float u = v - r.x;
    const float2 ab = __half22float2(*(const __half2*)&r.z);  /* A, dk */
    const float2 cd = __half22float2(*(const __half2*)&r.w);  /* C, D  */
    const float num = u * fmaf(ab.x, u, ab.y);
    const float den = fmaf(u, fmaf(cd.x, u, cd.y), 1.0f);
    return r.y + __fdividef(num, den);  /* identity rows: y = 0 + v/1 = v */
}

__device__ __forceinline__ void eval_batch(
    const float* __restrict__ xv,
    const float* __restrict__ celld,
    const float4* __restrict__ recd,
    float* __restrict__ out, int i)
{
    int jj[U];
    #pragma unroll
    for (int u = 0; u < U; ++u) jj[u] = bin_of(xv[u], celld);
    #pragma unroll
    for (int u = 0; u < U; ++u)
        __stcs(out + i + u * STRIDE, eval1(xv[u], jj[u], recd));
}

__global__ __launch_bounds__(THREADS, 2) void rqspline_kernel(
    const float* __restrict__ x,
    const float* __restrict__ bw,
    const float* __restrict__ bh,
    const float* __restrict__ ks,
    float* __restrict__ out,
    int total)
{
    extern __shared__ __align__(16) char smem[];
    float4* rec  = (float4*)smem;
    float*  cell = (float*) (smem + OFF_CELL);
    float*  hi   = (float*) (smem + OFF_HI);

    const int t = threadIdx.x;
    const int tid = blockIdx.x * THREADS + t;

    /* ---- prefetch batch 0 BEFORE table build: LDGs fly during build ---- */
    float xc[U];
    const bool full0 = (tid + (U - 1) * STRIDE < total);
    if (full0) {
        #pragma unroll
        for (int u = 0; u < U; ++u) xc[u] = __ldcs(x + tid + u * STRIDE);
    }

    /* ---- phase 1: per-dim records; rows 0 and 33 encode identity ---- */
    if (t < NDIM) {
        const __half2 h01_id = __floats2half2_rn(0.0f, 1.0f);  /* A=0, dk=1 */
        const __half2 h23_id = __floats2half2_rn(0.0f, 0.0f);  /* C=0, D=0  */
        float4 rid;
        rid.x = 0.0f; rid.y = 0.0f;
        rid.z = __uint_as_float(*(const unsigned*)&h01_id);
        rid.w = __uint_as_float(*(const unsigned*)&h23_id);
        rec[t] = rid;
        rec[(NROWS - 1) * NDIM + t] = rid;

        float cx = RMIN, cy = RMIN;
        #pragma unroll
        for (int jb = 0; jb < NBINS; ++jb) {
            const float nx = cx + bw[t * NBINS + jb];  /* reference fp32 cumsum */
            const float ny = cy + bh[t * NBINS + jb];
            const float wf = nx - cx;
            const float hf = ny - cy;
            const float dk  = (jb == 0) ? 1.0f : ks[t * (NBINS - 1) + jb - 1];
            const float dk1 = (jb == NBINS - 1) ? 1.0f : ks[t * (NBINS - 1) + jb];

            const float s = hf / wf;
            const float c = dk + dk1 - 2.0f * s;
            const float A = (s - dk) / wf;
            const float C = -c / (hf * wf);
            const float D = c / hf;

            float4 r;
            r.x = cx; r.y = cy;
            const __half2 h01 = __floats2half2_rn(A, dk);
            const __half2 h23 = __floats2half2_rn(C, D);
            r.z = __uint_as_float(*(const unsigned*)&h01);
            r.w = __uint_as_float(*(const unsigned*)&h23);
            rec[(jb + 1) * NDIM + t] = r;
            cx = nx; cy = ny;
        }
        hi[t] = cx;                /* kx[32] */
    }
    __syncthreads();

    /* ---- phase 2: cell table; boundaries read from rec[j+1].x ---- */
    const float* recf = (const float*)rec;
    for (int e = t; e < NCELL * NDIM; e += THREADS) {
        const int c = e >> 6, d = e & (NDIM - 1);
        float bnd; int jlo;
        if (c == 0) {              /* spans (-inf, first cell end) */
            bnd = RMIN; jlo = 0;   /* v<-5 -> row 0; v>=-5 -> row 1 */
        } else {
            const float cs = RMIN + (float)c * (10.0f / 65.0f);
            int j0 = min(c >> 1, NBINS - 1);
            while (j0 > 0 &&
                   recf[((j0 + 1) << 8) + (d << 2)] > cs) --j0;
            while (j0 < NBINS - 1 &&
                   recf[((j0 + 2) << 8) + (d << 2)] <= cs) ++j0;
            jlo = j0 + 1;
            bnd = (j0 + 1 < NBINS) ? recf[((j0 + 2) << 8) + (d << 2)] : hi[d];
        }
        cell[c * NDIM + d] =
            __int_as_float((__float_as_int(bnd) & ~63) | jlo);
    }
    __syncthreads();

    /* ---- phase 3: software-pipelined streaming eval ---- */
    const int d = tid & (NDIM - 1);      /* loop-invariant: STRIDE % 64 == 0 */
    const float4* recd  = rec  + d;
    const float*  celld = cell + d;

    int i = tid;
    for (; i + (2 * U - 1) * STRIDE < total; i += U * STRIDE) {
        float xn[U];
        #pragma unroll
        for (int u = 0; u < U; ++u)          /* next batch LDGs in flight */
            xn[u] = __ldcs(x + i + (U + u) * STRIDE);
        eval_batch(xc, celld, recd, out, i);
        #pragma unroll
        for (int u = 0; u < U; ++u) xc[u] = xn[u];
    }
    if (full0 && i + (U - 1) * STRIDE < total) {
        eval_batch(xc, celld, recd, out, i);
        i += U * STRIDE;
    }
    for (; i < total; i += STRIDE) {
        const float v = __ldcs(x + i);
        __stcs(out + i, eval1(v, bin_of(v, celld), recd));
    }
}

extern "C" void kernel_launch(void* const* d_in, const int* in_sizes, int n_in,
                              void* d_out, int out_size) {
    const float* x  = (const float*)d_in[0];
    const float* bw = (const float*)d_in[1];
    const float* bh = (const float*)d_in[2];
    const float* ks = (const float*)d_in[3];
    float* out = (float*)d_out;
    const int total = in_sizes[0];

    cudaFuncSetAttribute(rqspline_kernel,
                         cudaFuncAttributeMaxDynamicSharedMemorySize, SMEM_BYTES);
    rqspline_kernel<<<BLOCKS, THREADS, SMEM_BYTES>>>(x, bw, bh, ks, out, total);
}